// round 4
// baseline (speedup 1.0000x reference)
#include <cuda_runtime.h>
#include <cstdint>

#define GRID_DIM   128
#define U_PIX      8192
#define N_TRK      3000
#define M_NEIGH    16
#define T_SIG      400
#define ADC_SAMPLE 50
#define NBINS      200          // T_TOTAL / ADC_SAMPLE
#define MAX_BINS   9            // ceil((400+49)/50)
#define GAIN       0.25f
#define PEDESTAL   74.0f
#define ADC_MAX    255.0f

// Scratch (allocation-free rule: __device__ globals).
// g_acc is zero at module load; k_final re-zeroes every row it reads, so each
// call (correctness run, capture, every replay) sees a zeroed accumulator.
__device__ int   g_lut[GRID_DIM * GRID_DIM];     // (y,x) -> unique pixel id, -1 = none
__device__ float g_acc[U_PIX * NBINS];           // per-pixel per-50-sample-bin sums

// ---------------------------------------------------------------------------
// Kernel 1: invalidate LUT (tiny: 64 KB)
// ---------------------------------------------------------------------------
__global__ void k_init() {
    int tid = blockIdx.x * blockDim.x + threadIdx.x;
    if (tid < GRID_DIM * GRID_DIM) g_lut[tid] = -1;
}

// ---------------------------------------------------------------------------
// Kernel 2: scatter unique_pix into the LUT (coords unique by construction)
// ---------------------------------------------------------------------------
__global__ void k_lut(const int2* __restrict__ unique_pix) {
    int u = blockIdx.x * blockDim.x + threadIdx.x;
    if (u >= U_PIX) return;
    int2 c = unique_pix[u];
    g_lut[c.x * GRID_DIM + c.y] = u;
}

// ---------------------------------------------------------------------------
// Kernel 3: one warp per (track, neighbor) pair.
// Coalesced float4 loads (exactly 76.8 MB read, MLP=4/lane). Each 4-elem chunk
// spans <=2 adjacent bins; split into lo/hi and scatter into a 9-register
// per-lane bin vector with predicated adds (no atomics, no smem). One 5-stage
// butterfly reduces all 9 bins with full ILP; lanes 0..8 issue 9 REDGs.
// ---------------------------------------------------------------------------
__global__ void k_accum(const int2*  __restrict__ neigh,
                        const float* __restrict__ sig,
                        const int*   __restrict__ starts) {
    int gwarp = (blockIdx.x * blockDim.x + threadIdx.x) >> 5;
    int lane  = threadIdx.x & 31;
    if (gwarp >= N_TRK * M_NEIGH) return;

    int2 c = neigh[gwarp];
    if (c.x < 0) return;                          // dead channel -> discard

    int pid = g_lut[c.x * GRID_DIM + c.y];
    if (pid < 0) return;

    int n     = gwarp >> 4;                       // M_NEIGH = 16
    int start = starts[n];
    int b0    = start / ADC_SAMPLE;               // 0..191
    int rel0  = start - b0 * ADC_SAMPLE;          // 0..49

    const float4* s4 = reinterpret_cast<const float4*>(sig + (size_t)gwarp * T_SIG);

    // Issue all loads up front (MLP = 4)
    float4 f[4];
    #pragma unroll
    for (int j = 0; j < 4; ++j) {
        int cidx = j * 32 + lane;                 // 0..127, valid < 100
        f[j] = (cidx < 100) ? s4[cidx] : make_float4(0.f, 0.f, 0.f, 0.f);
    }

    float v[MAX_BINS];
    #pragma unroll
    for (int i = 0; i < MAX_BINS; ++i) v[i] = 0.0f;

    #pragma unroll
    for (int j = 0; j < 4; ++j) {
        int cidx = j * 32 + lane;
        if (cidx < 100) {
            int   r0  = rel0 + 4 * cidx;          // rel pos of f[j].x, 0..445
            int   li0 = r0 / 50;                  // bin of first elem, 0..8
            int   li3 = (r0 + 3) / 50;            // bin of last elem, <=8
            float tot = (f[j].x + f[j].y) + (f[j].z + f[j].w);
            float hiv = 0.0f;
            if (li0 != li3) {
                int nhi = r0 + 4 - li3 * 50;      // elems in upper bin: 1..3
                hiv = f[j].w;
                if (nhi >= 2) hiv += f[j].z;
                if (nhi >= 3) hiv += f[j].y;
            }
            float lov = tot - hiv;
            // predicated register scatter (li3 == li0 or li0+1)
            #pragma unroll
            for (int i = 0; i < MAX_BINS; ++i) {
                if (li0     == i) v[i] += lov;
                if (li0 + 1 == i) v[i] += hiv;    // hiv==0 when no split
            }
        }
    }

    // One butterfly over the 9-vector: 5 stages, 9 independent adds per stage
    #pragma unroll
    for (int o = 16; o > 0; o >>= 1) {
        #pragma unroll
        for (int i = 0; i < MAX_BINS; ++i)
            v[i] += __shfl_xor_sync(0xffffffffu, v[i], o);
    }

    // lane i owns bin i (constant-index selection, stays in registers)
    float mine = 0.0f;
    #pragma unroll
    for (int i = 0; i < MAX_BINS; ++i)
        if (lane == i) mine = v[i];

    if (lane < MAX_BINS)                          // b0+8 <= 199 always
        atomicAdd(&g_acc[(size_t)pid * NBINS + b0 + lane], mine);
}

// ---------------------------------------------------------------------------
// Kernel 4: one warp per pixel row. Both chunk loads issued up front; two warp
// scans interleaved in one 5-stage shuffle chain; fused affine + clip;
// re-zeroes the g_acc row for the next call.
// ---------------------------------------------------------------------------
__global__ void k_final(float* __restrict__ out) {
    int gwarp = (blockIdx.x * blockDim.x + threadIdx.x) >> 5;
    int lane  = threadIdx.x & 31;
    if (gwarp >= U_PIX) return;

    float4* row4 = reinterpret_cast<float4*>(g_acc + (size_t)gwarp * NBINS);
    float4* out4 = reinterpret_cast<float4*>(out + (size_t)gwarp * NBINS);

    const float4 z4 = make_float4(0.f, 0.f, 0.f, 0.f);
    bool act1 = (lane < NBINS / 4 - 32);          // lanes 0..17

    float4 x0 = row4[lane];                       // elements 0..127
    float4 x1 = act1 ? row4[32 + lane] : z4;      // elements 128..199

    x0.y += x0.x;  x0.z += x0.y;  x0.w += x0.z;
    x1.y += x1.x;  x1.z += x1.y;  x1.w += x1.z;
    float s0 = x0.w, s1 = x1.w;

    float i0 = s0, i1 = s1;
    #pragma unroll
    for (int o = 1; o < 32; o <<= 1) {
        float u0 = __shfl_up_sync(0xffffffffu, i0, o);
        float u1 = __shfl_up_sync(0xffffffffu, i1, o);
        if (lane >= o) { i0 += u0; i1 += u1; }
    }
    float tot0  = __shfl_sync(0xffffffffu, i0, 31);
    float base0 = i0 - s0;
    float base1 = tot0 + (i1 - s1);

    float4 r;
    r.x = fminf(fmaxf((x0.x + base0) * GAIN + PEDESTAL, 0.0f), ADC_MAX);
    r.y = fminf(fmaxf((x0.y + base0) * GAIN + PEDESTAL, 0.0f), ADC_MAX);
    r.z = fminf(fmaxf((x0.z + base0) * GAIN + PEDESTAL, 0.0f), ADC_MAX);
    r.w = fminf(fmaxf((x0.w + base0) * GAIN + PEDESTAL, 0.0f), ADC_MAX);
    out4[lane] = r;
    row4[lane] = z4;                              // re-zero accumulator row
    if (act1) {
        r.x = fminf(fmaxf((x1.x + base1) * GAIN + PEDESTAL, 0.0f), ADC_MAX);
        r.y = fminf(fmaxf((x1.y + base1) * GAIN + PEDESTAL, 0.0f), ADC_MAX);
        r.z = fminf(fmaxf((x1.z + base1) * GAIN + PEDESTAL, 0.0f), ADC_MAX);
        r.w = fminf(fmaxf((x1.w + base1) * GAIN + PEDESTAL, 0.0f), ADC_MAX);
        out4[32 + lane] = r;
        row4[32 + lane] = z4;
    }
}

// ---------------------------------------------------------------------------
// Launch
// ---------------------------------------------------------------------------
extern "C" void kernel_launch(void* const* d_in, const int* in_sizes, int n_in,
                              void* d_out, int out_size) {
    const int2*  neigh  = (const int2*) d_in[0];   // (3000, 16, 2) int32
    const int2*  upix   = (const int2*) d_in[1];   // (8192, 2) int32
    const float* sig    = (const float*)d_in[2];   // (3000, 16, 400) float32
    const int*   starts = (const int*)  d_in[3];   // (3000,) int32
    float*       out    = (float*)      d_out;     // (8192, 200) float32

    (void)in_sizes; (void)n_in; (void)out_size;

    k_init<<<(GRID_DIM * GRID_DIM + 255) / 256, 256>>>();
    k_lut<<<(U_PIX + 255) / 256, 256>>>(upix);

    {
        int total_warps = N_TRK * M_NEIGH;         // 48000
        int threads = 256;
        int blocks  = (total_warps * 32 + threads - 1) / threads;
        k_accum<<<blocks, threads>>>(neigh, sig, starts);
    }
    {
        int threads = 256;
        int blocks  = (U_PIX * 32 + threads - 1) / threads;   // 1024
        k_final<<<blocks, threads>>>(out);
    }
}

// round 5
// speedup vs baseline: 1.7036x; 1.7036x over previous
#include <cuda_runtime.h>
#include <cstdint>

#define GRID_DIM   128
#define U_PIX      8192
#define N_TRK      3000
#define M_NEIGH    16
#define T_SIG      400
#define ADC_SAMPLE 50
#define NBINS      200          // T_TOTAL / ADC_SAMPLE
#define MAX_BINS   9            // ceil((400+49)/50)
#define GAIN       0.25f
#define PEDESTAL   74.0f
#define ADC_MAX    255.0f

// Scratch (allocation-free rule: __device__ globals)
__device__ int   g_lut[GRID_DIM * GRID_DIM];     // (y,x) -> unique pixel id, -1 = none
__device__ float g_acc[U_PIX * NBINS];           // per-pixel per-50-sample-bin sums

// ---------------------------------------------------------------------------
// Kernel 1: zero accumulator (vectorized) + invalidate LUT   [R2 behavior]
// ---------------------------------------------------------------------------
__global__ void k_init() {
    int tid    = blockIdx.x * blockDim.x + threadIdx.x;
    int stride = gridDim.x * blockDim.x;
    for (int i = tid; i < GRID_DIM * GRID_DIM; i += stride) g_lut[i] = -1;
    float4* acc4 = reinterpret_cast<float4*>(g_acc);
    const int n4 = (U_PIX * NBINS) / 4;
    for (int i = tid; i < n4; i += stride) acc4[i] = make_float4(0.f, 0.f, 0.f, 0.f);
}

// ---------------------------------------------------------------------------
// Kernel 2: scatter unique_pix into the LUT (coords unique by construction)
// ---------------------------------------------------------------------------
__global__ void k_lut(const int2* __restrict__ unique_pix) {
    int u = blockIdx.x * blockDim.x + threadIdx.x;
    if (u >= U_PIX) return;
    int2 c = unique_pix[u];
    g_lut[c.x * GRID_DIM + c.y] = u;
}

// ---------------------------------------------------------------------------
// Kernel 3: one warp per (track, neighbor) pair.
// Stage the 400-sample signal into smem with perfectly coalesced float4 loads
// (13 L1 wavefronts/warp, exact traffic), then lanes 0..8 serially sum their
// own bin's <=50 floats from smem (conflict-free banks) and issue one REDG.
// No shuffles, no shared atomics.
// ---------------------------------------------------------------------------
__global__ void k_accum(const int2*  __restrict__ neigh,
                        const float* __restrict__ sig,
                        const int*   __restrict__ starts) {
    __shared__ float sbuf[8][T_SIG];              // 8 warps * 1600 B = 12.8 KB

    int gwarp = (blockIdx.x * blockDim.x + threadIdx.x) >> 5;
    int lane  = threadIdx.x & 31;
    int wib   = threadIdx.x >> 5;
    if (gwarp >= N_TRK * M_NEIGH) return;

    int2 c = neigh[gwarp];
    if (c.x < 0) return;                          // dead channel -> discard

    int pid = g_lut[c.x * GRID_DIM + c.y];
    if (pid < 0) return;

    int start = starts[gwarp >> 4];               // M_NEIGH = 16
    int b0    = start / ADC_SAMPLE;               // 0..191
    int rel0  = start - b0 * ADC_SAMPLE;          // 0..49

    // Coalesced copy gmem -> smem (100 float4 per signal)
    const float4* s4  = reinterpret_cast<const float4*>(sig + (size_t)gwarp * T_SIG);
    float4*       sb4 = reinterpret_cast<float4*>(sbuf[wib]);
    #pragma unroll
    for (int j = 0; j < 4; ++j) {
        int cidx = j * 32 + lane;                 // 0..127, valid < 100
        if (cidx < 100) sb4[cidx] = s4[cidx];
    }
    __syncwarp();

    // lane i sums bin i: samples t in [i*50-rel0, (i+1)*50-rel0) clipped to [0,400)
    if (lane < MAX_BINS) {
        int lo = lane * ADC_SAMPLE - rel0;        if (lo < 0)     lo = 0;
        int hi = (lane + 1) * ADC_SAMPLE - rel0;  if (hi > T_SIG) hi = T_SIG;

        const float* p = sbuf[wib];
        float a0 = 0.f, a1 = 0.f, a2 = 0.f, a3 = 0.f;
        int t = lo;
        for (; t + 4 <= hi; t += 4) {             // 4 accumulators: short dep chains
            a0 += p[t];  a1 += p[t + 1];  a2 += p[t + 2];  a3 += p[t + 3];
        }
        for (; t < hi; ++t) a0 += p[t];
        float s = (a0 + a1) + (a2 + a3);

        atomicAdd(&g_acc[(size_t)pid * NBINS + b0 + lane], s);  // b0+8 <= 199
    }
}

// ---------------------------------------------------------------------------
// Kernel 4: one warp per pixel row. Both chunk loads up front; two interleaved
// warp scans in one 5-stage shuffle chain; fused affine + clip. (No re-zero:
// k_init owns accumulator zeroing.)
// ---------------------------------------------------------------------------
__global__ void k_final(float* __restrict__ out) {
    int gwarp = (blockIdx.x * blockDim.x + threadIdx.x) >> 5;
    int lane  = threadIdx.x & 31;
    if (gwarp >= U_PIX) return;

    const float4* row4 = reinterpret_cast<const float4*>(g_acc + (size_t)gwarp * NBINS);
    float4*       out4 = reinterpret_cast<float4*>(out + (size_t)gwarp * NBINS);

    const float4 z4 = make_float4(0.f, 0.f, 0.f, 0.f);
    bool act1 = (lane < NBINS / 4 - 32);          // lanes 0..17

    float4 x0 = row4[lane];                       // elements 0..127
    float4 x1 = act1 ? row4[32 + lane] : z4;      // elements 128..199

    x0.y += x0.x;  x0.z += x0.y;  x0.w += x0.z;
    x1.y += x1.x;  x1.z += x1.y;  x1.w += x1.z;
    float s0 = x0.w, s1 = x1.w;

    float i0 = s0, i1 = s1;
    #pragma unroll
    for (int o = 1; o < 32; o <<= 1) {
        float u0 = __shfl_up_sync(0xffffffffu, i0, o);
        float u1 = __shfl_up_sync(0xffffffffu, i1, o);
        if (lane >= o) { i0 += u0; i1 += u1; }
    }
    float tot0  = __shfl_sync(0xffffffffu, i0, 31);
    float base0 = i0 - s0;
    float base1 = tot0 + (i1 - s1);

    float4 r;
    r.x = fminf(fmaxf((x0.x + base0) * GAIN + PEDESTAL, 0.0f), ADC_MAX);
    r.y = fminf(fmaxf((x0.y + base0) * GAIN + PEDESTAL, 0.0f), ADC_MAX);
    r.z = fminf(fmaxf((x0.z + base0) * GAIN + PEDESTAL, 0.0f), ADC_MAX);
    r.w = fminf(fmaxf((x0.w + base0) * GAIN + PEDESTAL, 0.0f), ADC_MAX);
    out4[lane] = r;
    if (act1) {
        r.x = fminf(fmaxf((x1.x + base1) * GAIN + PEDESTAL, 0.0f), ADC_MAX);
        r.y = fminf(fmaxf((x1.y + base1) * GAIN + PEDESTAL, 0.0f), ADC_MAX);
        r.z = fminf(fmaxf((x1.z + base1) * GAIN + PEDESTAL, 0.0f), ADC_MAX);
        r.w = fminf(fmaxf((x1.w + base1) * GAIN + PEDESTAL, 0.0f), ADC_MAX);
        out4[32 + lane] = r;
    }
}

// ---------------------------------------------------------------------------
// Launch
// ---------------------------------------------------------------------------
extern "C" void kernel_launch(void* const* d_in, const int* in_sizes, int n_in,
                              void* d_out, int out_size) {
    const int2*  neigh  = (const int2*) d_in[0];   // (3000, 16, 2) int32
    const int2*  upix   = (const int2*) d_in[1];   // (8192, 2) int32
    const float* sig    = (const float*)d_in[2];   // (3000, 16, 400) float32
    const int*   starts = (const int*)  d_in[3];   // (3000,) int32
    float*       out    = (float*)      d_out;     // (8192, 200) float32

    (void)in_sizes; (void)n_in; (void)out_size;

    k_init<<<1024, 256>>>();
    k_lut<<<(U_PIX + 255) / 256, 256>>>(upix);

    {
        int total_warps = N_TRK * M_NEIGH;         // 48000
        int threads = 256;                         // 8 warps/block -> 6000 blocks
        int blocks  = (total_warps * 32 + threads - 1) / threads;
        k_accum<<<blocks, threads>>>(neigh, sig, starts);
    }
    {
        int threads = 256;
        int blocks  = (U_PIX * 32 + threads - 1) / threads;   // 1024
        k_final<<<blocks, threads>>>(out);
    }
}

// round 6
// speedup vs baseline: 1.9621x; 1.1517x over previous
#include <cuda_runtime.h>
#include <cstdint>

#define GRID_DIM   128
#define U_PIX      8192
#define N_TRK      3000
#define M_NEIGH    16
#define T_SIG      400
#define ADC_SAMPLE 50
#define NBINS      200          // T_TOTAL / ADC_SAMPLE
#define MAX_BINS   9            // ceil((400+49)/50)
#define GAIN       0.25f
#define PEDESTAL   74.0f
#define ADC_MAX    255.0f

// Scratch (allocation-free rule: __device__ globals)
// g_lut is NEVER invalidated: lookups are verified against unique_pix, so
// stale entries (zero-init on first call, deterministic rewrites on replays)
// are harmless.
__device__ int   g_lut[GRID_DIM * GRID_DIM];     // (y,x) -> candidate pixel id
__device__ float g_acc[U_PIX * NBINS];           // per-pixel per-bin sums

// ---------------------------------------------------------------------------
// Kernel 1: zero accumulator (vectorized) + scatter LUT, fused in one launch.
// ---------------------------------------------------------------------------
__global__ void k_prep(const int2* __restrict__ unique_pix) {
    int tid    = blockIdx.x * blockDim.x + threadIdx.x;
    int stride = gridDim.x * blockDim.x;
    float4* acc4 = reinterpret_cast<float4*>(g_acc);
    const int n4 = (U_PIX * NBINS) / 4;           // 409600
    for (int i = tid; i < n4; i += stride) acc4[i] = make_float4(0.f, 0.f, 0.f, 0.f);
    if (tid < U_PIX) {
        int2 c = unique_pix[tid];
        g_lut[c.x * GRID_DIM + c.y] = tid;
    }
}

// ---------------------------------------------------------------------------
// Kernel 2: one warp per (track, neighbor) pair.  [R2 structure, proven best]
// 18 segment loads up front (MLP 18), one 5-stage butterfly over the
// 9-register bin vector (full ILP), lanes 0..8 flush with one REDG each.
// LUT hit verified against unique_pix coordinates.
// ---------------------------------------------------------------------------
__global__ void k_accum(const int2*  __restrict__ neigh,
                        const int2*  __restrict__ upix,
                        const float* __restrict__ sig,
                        const int*   __restrict__ starts) {
    int gwarp = (blockIdx.x * blockDim.x + threadIdx.x) >> 5;
    int lane  = threadIdx.x & 31;
    if (gwarp >= N_TRK * M_NEIGH) return;

    int2 c = neigh[gwarp];
    if (c.x < 0) return;                          // dead channel -> discard

    int  pid = g_lut[c.x * GRID_DIM + c.y];       // candidate (may be stale)
    int2 u   = upix[pid];
    if (u.x != c.x || u.y != c.y) return;         // verify: reject stale/no-match

    int start = starts[gwarp >> 4];               // M_NEIGH = 16
    int b0    = start / ADC_SAMPLE;               // 0..191
    int rel0  = start - b0 * ADC_SAMPLE;          // 0..49

    const float* s = sig + (size_t)gwarp * T_SIG;

    // Per-bin segment partial sums (bin b0+i covers [i*50-rel0, (i+1)*50-rel0))
    float v[MAX_BINS];
    #pragma unroll
    for (int i = 0; i < MAX_BINS; ++i) {
        int lo = i * ADC_SAMPLE - rel0;           if (lo < 0)     lo = 0;
        int hi = (i + 1) * ADC_SAMPLE - rel0;     if (hi > T_SIG) hi = T_SIG;
        int t  = lo + lane;
        float a = (t      < hi) ? s[t]      : 0.0f;
        float b = (t + 32 < hi) ? s[t + 32] : 0.0f;  // segment length <= 50
        v[i] = a + b;
    }

    // One butterfly over the 9-vector: 5 stages, 9 independent adds per stage
    #pragma unroll
    for (int o = 16; o > 0; o >>= 1) {
        #pragma unroll
        for (int i = 0; i < MAX_BINS; ++i)
            v[i] += __shfl_xor_sync(0xffffffffu, v[i], o);
    }

    float mine = 0.0f;
    #pragma unroll
    for (int i = 0; i < MAX_BINS; ++i)
        if (lane == i) mine = v[i];

    if (lane < MAX_BINS)                          // b0+8 <= 199 always
        atomicAdd(&g_acc[(size_t)pid * NBINS + b0 + lane], mine);
}

// ---------------------------------------------------------------------------
// Kernel 3: TWO rows per warp. All 4 chunk loads issued up front; FOUR warp
// scans interleaved in one 5-stage shuffle chain (4x ILP); fused affine+clip.
// ---------------------------------------------------------------------------
__global__ void k_final(float* __restrict__ out) {
    int gwarp = (blockIdx.x * blockDim.x + threadIdx.x) >> 5;  // 0..4095
    int lane  = threadIdx.x & 31;
    if (gwarp >= U_PIX / 2) return;

    int rowA = gwarp * 2, rowB = rowA + 1;
    const float4* a4 = reinterpret_cast<const float4*>(g_acc + (size_t)rowA * NBINS);
    const float4* b4 = reinterpret_cast<const float4*>(g_acc + (size_t)rowB * NBINS);
    float4* oa4 = reinterpret_cast<float4*>(out + (size_t)rowA * NBINS);
    float4* ob4 = reinterpret_cast<float4*>(out + (size_t)rowB * NBINS);

    const float4 z4 = make_float4(0.f, 0.f, 0.f, 0.f);
    bool act1 = (lane < NBINS / 4 - 32);          // lanes 0..17

    float4 xa0 = a4[lane];
    float4 xb0 = b4[lane];
    float4 xa1 = act1 ? a4[32 + lane] : z4;
    float4 xb1 = act1 ? b4[32 + lane] : z4;

    xa0.y += xa0.x;  xa0.z += xa0.y;  xa0.w += xa0.z;
    xa1.y += xa1.x;  xa1.z += xa1.y;  xa1.w += xa1.z;
    xb0.y += xb0.x;  xb0.z += xb0.y;  xb0.w += xb0.z;
    xb1.y += xb1.x;  xb1.z += xb1.y;  xb1.w += xb1.z;
    float sa0 = xa0.w, sa1 = xa1.w, sb0 = xb0.w, sb1 = xb1.w;

    float ia0 = sa0, ia1 = sa1, ib0 = sb0, ib1 = sb1;
    #pragma unroll
    for (int o = 1; o < 32; o <<= 1) {
        float ua0 = __shfl_up_sync(0xffffffffu, ia0, o);
        float ua1 = __shfl_up_sync(0xffffffffu, ia1, o);
        float ub0 = __shfl_up_sync(0xffffffffu, ib0, o);
        float ub1 = __shfl_up_sync(0xffffffffu, ib1, o);
        if (lane >= o) { ia0 += ua0; ia1 += ua1; ib0 += ub0; ib1 += ub1; }
    }
    float totA0 = __shfl_sync(0xffffffffu, ia0, 31);
    float totB0 = __shfl_sync(0xffffffffu, ib0, 31);
    float baseA0 = ia0 - sa0;
    float baseA1 = totA0 + (ia1 - sa1);
    float baseB0 = ib0 - sb0;
    float baseB1 = totB0 + (ib1 - sb1);

    float4 r;
    #define ADCV(x, b) fminf(fmaxf(((x) + (b)) * GAIN + PEDESTAL, 0.0f), ADC_MAX)
    r.x = ADCV(xa0.x, baseA0); r.y = ADCV(xa0.y, baseA0);
    r.z = ADCV(xa0.z, baseA0); r.w = ADCV(xa0.w, baseA0);
    oa4[lane] = r;
    r.x = ADCV(xb0.x, baseB0); r.y = ADCV(xb0.y, baseB0);
    r.z = ADCV(xb0.z, baseB0); r.w = ADCV(xb0.w, baseB0);
    ob4[lane] = r;
    if (act1) {
        r.x = ADCV(xa1.x, baseA1); r.y = ADCV(xa1.y, baseA1);
        r.z = ADCV(xa1.z, baseA1); r.w = ADCV(xa1.w, baseA1);
        oa4[32 + lane] = r;
        r.x = ADCV(xb1.x, baseB1); r.y = ADCV(xb1.y, baseB1);
        r.z = ADCV(xb1.z, baseB1); r.w = ADCV(xb1.w, baseB1);
        ob4[32 + lane] = r;
    }
    #undef ADCV
}

// ---------------------------------------------------------------------------
// Launch: 3 kernels total
// ---------------------------------------------------------------------------
extern "C" void kernel_launch(void* const* d_in, const int* in_sizes, int n_in,
                              void* d_out, int out_size) {
    const int2*  neigh  = (const int2*) d_in[0];   // (3000, 16, 2) int32
    const int2*  upix   = (const int2*) d_in[1];   // (8192, 2) int32
    const float* sig    = (const float*)d_in[2];   // (3000, 16, 400) float32
    const int*   starts = (const int*)  d_in[3];   // (3000,) int32
    float*       out    = (float*)      d_out;     // (8192, 200) float32

    (void)in_sizes; (void)n_in; (void)out_size;

    k_prep<<<1024, 256>>>(upix);

    {
        int total_warps = N_TRK * M_NEIGH;         // 48000
        int threads = 256;
        int blocks  = (total_warps * 32 + threads - 1) / threads;
        k_accum<<<blocks, threads>>>(neigh, upix, sig, starts);
    }
    {
        int warps   = U_PIX / 2;                   // 4096
        int threads = 256;
        int blocks  = (warps * 32 + threads - 1) / threads;   // 512
        k_final<<<blocks, threads>>>(out);
    }
}